// round 12
// baseline (speedup 1.0000x reference)
#include <cuda_runtime.h>
#include <math.h>
#include <stdint.h>

#define NN 100000
#define EE 640000
#define BB 2000
#define ND 256
#define ED 128
#define EMBD 256
#define LBLK 3

// ------------------------- scratch (no allocations allowed) -------------------------
__device__ float g_hn0[NN * ND];
__device__ float g_hn1[NN * ND];
__device__ float g_he0[EE * ED];
__device__ float g_he1[EE * ED];
__device__ float g_agg[NN * ND];
__device__ float g_U[NN * 256];       // [U_src | U_dst] per node
__device__ float g_Msrc[NN * 256];    // hn @ W_msg_top per node
__device__ float g_Wsd[256 * 256];    // packed [Ws | Wd]
__device__ float g_dist[EE];
__device__ int   g_src[EE];
__device__ int   g_dst[EE];
__device__ int   g_bn[NN];
__device__ int   g_be[EE];
__device__ int   g_is64;
__device__ float g_sum_n[BB * ND];
__device__ float g_sum_e[BB * ED];
__device__ float g_cnt_n[BB];
__device__ float g_cnt_e[BB];
__device__ float g_hsub[BB * (ND + ED)];
__device__ float g_h1[BB * 2 * EMBD];

// ------------------------- f32x2 helpers -------------------------
__device__ __forceinline__ void unpack2(unsigned long long v, float& lo, float& hi) {
    asm("mov.b64 {%0, %1}, %2;" : "=f"(lo), "=f"(hi) : "l"(v));
}
#define FMA2(acc, a, b) \
    asm("fma.rn.f32x2 %0, %1, %2, %0;" : "+l"(acc) : "l"(a), "l"(b))
#define LDS_V2U64(x, y, addr) \
    asm("ld.shared.v2.u64 {%0, %1}, [%2];" : "=l"(x), "=l"(y) : "r"(addr))

__device__ __forceinline__ uint32_t smem_u32(const void* p) {
    uint32_t a;
    asm("{ .reg .u64 t; cvta.to.shared.u64 t, %1; cvt.u32.u64 %0, t; }" : "=r"(a) : "l"(p));
    return a;
}

// ------------------------- dtype detection (int32 vs int64 indices) -------------------------
__global__ void k_detect(const unsigned int* __restrict__ u) {
    if (threadIdx.x != 0 || blockIdx.x != 0) return;
    int odd_nonzero = 0;
    for (int i = 0; i < 64; i++)
        if (u[2 * i + 1] != 0u) odd_nonzero++;
    g_is64 = (odd_nonzero == 0) ? 1 : 0;
}

__global__ void k_cvt_off(const void* __restrict__ p, int n, int off,
                          int* __restrict__ outp) {
    int i = blockIdx.x * 256 + threadIdx.x;
    if (i >= n) return;
    if (g_is64) outp[i] = (int)((const long long*)p)[off + i];
    else        outp[i] = ((const int*)p)[off + i];
}

// ------------------------- prep -------------------------
__global__ void k_prep_edge(const float* __restrict__ pos) {
    int e = blockIdx.x * 256 + threadIdx.x;
    if (e >= EE) return;
    int s = g_src[e], d = g_dst[e];
    float dx = pos[d * 3 + 0] - pos[s * 3 + 0];
    float dy = pos[d * 3 + 1] - pos[s * 3 + 1];
    float dz = pos[d * 3 + 2] - pos[s * 3 + 2];
    g_dist[e] = sqrtf(dx * dx + dy * dy + dz * dz);
}

// pack W_sd[k][0:128] = W_eu[128+k][:], W_sd[k][128:256] = W_eu[384+k][:]
__global__ void k_pack_wsd(const float* __restrict__ Weu) {
    int i = blockIdx.x * 256 + threadIdx.x;
    if (i >= 256 * 256) return;
    int k = i >> 8, j = i & 255;
    float v = (j < 128) ? Weu[(128 + k) * 128 + j] : Weu[(384 + k) * 128 + (j - 128)];
    g_Wsd[i] = v;
}

// ------------------------- embeddings -------------------------
__global__ void k_embed_node(const float* __restrict__ hfeat,
                             const float* __restrict__ W,
                             float* __restrict__ outp) {
    __shared__ float sw[16 * 256];
    for (int i = threadIdx.x; i < 16 * 256; i += 256) sw[i] = W[i];
    __syncthreads();
    int c = threadIdx.x;
    int n0 = blockIdx.x * 8;
    for (int r = 0; r < 8; r++) {
        int n = n0 + r;
        if (n >= NN) return;
        float acc = 0.f;
#pragma unroll
        for (int k = 0; k < 16; k++) acc += hfeat[n * 16 + k] * sw[k * 256 + c];
        outp[(size_t)n * 256 + c] = acc;
    }
}

__global__ void k_embed_edge(const float* __restrict__ hfeat,
                             const float* __restrict__ W,
                             float* __restrict__ outp) {
    __shared__ float sw[5 * 128];
    for (int i = threadIdx.x; i < 5 * 128; i += 256) sw[i] = W[i];
    __syncthreads();
    int sub = threadIdx.x >> 7;
    int c   = threadIdx.x & 127;
    int e0  = blockIdx.x * 16 + sub;
    for (int r = 0; r < 16; r += 2) {
        int e = e0 + r;
        if (e >= EE) return;
        float acc = 0.f;
#pragma unroll
        for (int k = 0; k < 5; k++) acc += hfeat[e * 5 + k] * sw[k * 128 + c];
        outp[(size_t)e * 128 + c] = acc;
    }
}

// ------------------------- zero -------------------------
__global__ void k_zero(float* __restrict__ p, int n) {
    int i = blockIdx.x * blockDim.x + threadIdx.x;
    int str = gridDim.x * blockDim.x;
    for (; i < n; i += str) p[i] = 0.f;
}

// ---------- tiled SGEMM: FFMA2 inner, row-paired accumulators, B dup'd in SMEM ----------
// MODE 0 (edge):  A=he[E,128] K=128 N=128; epi: relu(acc+b+U[src][c]+U[dst][128+c]+dist*wdist[c])
// MODE 1 (msg):   A=he_new[E,128] K=128 N=256; epi: relu(acc+b+Msrc[src][c]) -> red.add agg[dst]
// MODE 2 (node):  A=[hn|agg] K=512 N=256; epi: hn + relu(acc+b)
// MODE 3 (mlp1):  A generic; relu(acc+b)
// MODE 4 (mlp2):  A generic; acc+b
// MODE 5 (plain): A generic; acc (no bias)
template <int MODE>
__global__ __launch_bounds__(256, 2) void gemm_k(
    const float* __restrict__ P0, const float* __restrict__ P1,
    const float* __restrict__ Wb, const float* __restrict__ bias,
    float* __restrict__ Cout, const float* __restrict__ Extra,
    const int* __restrict__ src, const int* __restrict__ dst,
    const float* __restrict__ distv, const float* __restrict__ G,
    const float* __restrict__ wdist,
    int Mrows, int Kdim, int Ncols)
{
    __shared__ __align__(16) float As[16][128];    // [k][row]
    __shared__ __align__(16) float Bs2[16][256];   // [k][2*col] duplicated pairs
    const int tid = threadIdx.x;
    const int tx = tid & 15, ty = tid >> 4;
    const int m0 = blockIdx.x * 128;
    const int n0 = blockIdx.y * 128;

    const uint32_t asb = smem_u32(As);
    const uint32_t bsb = smem_u32(Bs2);
    const uint32_t aAddr0 = asb + (uint32_t)ty * 32;   // rows ty*8..+7 -> 32B; +kk*512
    const uint32_t bAddr0 = bsb + (uint32_t)tx * 64;   // dup cols tx*8..+7 -> 64B; +kk*1024

    // acc2[i][j]: packed pair {row ty*8+2i, row ty*8+2i+1} at col tx*8+j
    unsigned long long acc2[4][8];
#pragma unroll
    for (int i = 0; i < 4; i++)
#pragma unroll
        for (int j = 0; j < 8; j++) acc2[i][j] = 0ull;

    const int ar  = tid & 127;
    const int ak0 = (tid >> 7) * 8;
    const int rowg = m0 + ar;
    const bool rvalid = (rowg < Mrows);

    const int KT = Kdim >> 4;            // all K are multiples of 16
    for (int kt = 0; kt < KT; kt++) {
        // ---- A tile: contiguous 8-float run per thread ----
        {
            const int k0 = kt * 16 + ak0;
            float4 v0 = make_float4(0.f, 0.f, 0.f, 0.f);
            float4 v1 = v0;
            if (rvalid) {
                const float* ap;
                if (MODE == 0 || MODE == 1)      ap = P0 + (size_t)rowg * 128 + k0;
                else if (MODE == 2)              ap = (k0 < 256) ? P0 + (size_t)rowg * 256 + k0
                                                                : P1 + (size_t)rowg * 256 + (k0 - 256);
                else                             ap = P0 + (size_t)rowg * Kdim + k0;
                v0 = *(const float4*)ap;
                v1 = *(const float4*)(ap + 4);
            }
            As[ak0 + 0][ar] = v0.x; As[ak0 + 1][ar] = v0.y;
            As[ak0 + 2][ar] = v0.z; As[ak0 + 3][ar] = v0.w;
            As[ak0 + 4][ar] = v1.x; As[ak0 + 5][ar] = v1.y;
            As[ak0 + 6][ar] = v1.z; As[ak0 + 7][ar] = v1.w;
        }
        // ---- B tile: load float4, store DUPLICATED pairs ----
#pragma unroll
        for (int r = 0; r < 2; r++) {
            int f  = tid + r * 256;
            int bk = f >> 5;
            int bc = (f & 31) * 4;
            int kg = kt * 16 + bk;
            float4 v = *(const float4*)(Wb + (size_t)kg * Ncols + n0 + bc);
            *(float4*)&Bs2[bk][bc * 2]     = make_float4(v.x, v.x, v.y, v.y);
            *(float4*)&Bs2[bk][bc * 2 + 4] = make_float4(v.z, v.z, v.w, v.w);
        }
        __syncthreads();
#pragma unroll
        for (int kk = 0; kk < 16; kk++) {
            const uint32_t aA = aAddr0 + (uint32_t)kk * 512;
            const uint32_t aB = bAddr0 + (uint32_t)kk * 1024;
            unsigned long long a2[4], bd[8];
            LDS_V2U64(a2[0], a2[1], aA);
            LDS_V2U64(a2[2], a2[3], aA + 16);
            LDS_V2U64(bd[0], bd[1], aB);
            LDS_V2U64(bd[2], bd[3], aB + 16);
            LDS_V2U64(bd[4], bd[5], aB + 32);
            LDS_V2U64(bd[6], bd[7], aB + 48);
#pragma unroll
            for (int i = 0; i < 4; i++)
#pragma unroll
                for (int j = 0; j < 8; j++) FMA2(acc2[i][j], a2[i], bd[j]);
        }
        __syncthreads();
    }

    // ---- epilogue ----
    const int cg0 = n0 + tx * 8;
    float bia[8], wd[8];
    if (MODE != 5) {
        *(float4*)&bia[0] = *(const float4*)(bias + cg0);
        *(float4*)&bia[4] = *(const float4*)(bias + cg0 + 4);
    }
    if (MODE == 0) {
        *(float4*)&wd[0] = *(const float4*)(wdist + cg0);
        *(float4*)&wd[4] = *(const float4*)(wdist + cg0 + 4);
    }

#pragma unroll
    for (int i = 0; i < 4; i++) {
        float vp[2][8];
#pragma unroll
        for (int j = 0; j < 8; j++) unpack2(acc2[i][j], vp[0][j], vp[1][j]);
#pragma unroll
        for (int p = 0; p < 2; p++) {
            int rg = m0 + ty * 8 + i * 2 + p;
            if (rg >= Mrows) continue;
            float* accr = vp[p];
            float vals[8];
            if (MODE == 0) {
                int sg = src[rg], dg = dst[rg];
                float dv = distv[rg];
                float gs[8], gd[8];
                *(float4*)&gs[0] = *(const float4*)(G + (size_t)sg * 256 + cg0);
                *(float4*)&gs[4] = *(const float4*)(G + (size_t)sg * 256 + cg0 + 4);
                *(float4*)&gd[0] = *(const float4*)(G + (size_t)dg * 256 + 128 + cg0);
                *(float4*)&gd[4] = *(const float4*)(G + (size_t)dg * 256 + 128 + cg0 + 4);
#pragma unroll
                for (int j = 0; j < 8; j++)
                    vals[j] = fmaxf(accr[j] + bia[j] + gs[j] + gd[j] + dv * wd[j], 0.f);
                *(float4*)(Cout + (size_t)rg * 128 + cg0)     = *(float4*)&vals[0];
                *(float4*)(Cout + (size_t)rg * 128 + cg0 + 4) = *(float4*)&vals[4];
            } else if (MODE == 1) {
                int sg = src[rg], dg = dst[rg];
                float gs[8];
                *(float4*)&gs[0] = *(const float4*)(G + (size_t)sg * 256 + cg0);
                *(float4*)&gs[4] = *(const float4*)(G + (size_t)sg * 256 + cg0 + 4);
#pragma unroll
                for (int j = 0; j < 8; j++)
                    vals[j] = fmaxf(accr[j] + bia[j] + gs[j], 0.f);
                float* ap = Cout + (size_t)dg * 256 + cg0;
                asm volatile("red.global.add.v4.f32 [%0], {%1,%2,%3,%4};"
                             :: "l"(ap), "f"(vals[0]), "f"(vals[1]), "f"(vals[2]), "f"(vals[3])
                             : "memory");
                asm volatile("red.global.add.v4.f32 [%0], {%1,%2,%3,%4};"
                             :: "l"(ap + 4), "f"(vals[4]), "f"(vals[5]), "f"(vals[6]), "f"(vals[7])
                             : "memory");
            } else if (MODE == 2) {
                float ex[8];
                *(float4*)&ex[0] = *(const float4*)(Extra + (size_t)rg * 256 + cg0);
                *(float4*)&ex[4] = *(const float4*)(Extra + (size_t)rg * 256 + cg0 + 4);
#pragma unroll
                for (int j = 0; j < 8; j++)
                    vals[j] = ex[j] + fmaxf(accr[j] + bia[j], 0.f);
                *(float4*)(Cout + (size_t)rg * 256 + cg0)     = *(float4*)&vals[0];
                *(float4*)(Cout + (size_t)rg * 256 + cg0 + 4) = *(float4*)&vals[4];
            } else {
#pragma unroll
                for (int j = 0; j < 8; j++) {
                    float v = accr[j] + (MODE == 5 ? 0.f : bia[j]);
                    if (MODE == 3) v = fmaxf(v, 0.f);
                    vals[j] = v;
                }
                *(float4*)(Cout + (size_t)rg * Ncols + cg0)     = *(float4*)&vals[0];
                *(float4*)(Cout + (size_t)rg * Ncols + cg0 + 4) = *(float4*)&vals[4];
            }
        }
    }
}

// ------------------------- pooling -------------------------
__global__ void k_count(const int* __restrict__ b, int n, float* __restrict__ cnt) {
    int i = blockIdx.x * 256 + threadIdx.x;
    if (i < n) atomicAdd(&cnt[b[i]], 1.f);
}

__global__ void k_pool_node(const float* __restrict__ hn) {
    int n0 = blockIdx.x * 128;
    int c = threadIdx.x;
    float acc = 0.f;
    int cur = -1;
    for (int i = 0; i < 128; i++) {
        int n = n0 + i;
        if (n >= NN) break;
        int b = g_bn[n];
        if (b != cur) {
            if (cur >= 0) atomicAdd(&g_sum_n[cur * ND + c], acc);
            cur = b; acc = 0.f;
        }
        acc += hn[(size_t)n * ND + c];
    }
    if (cur >= 0) atomicAdd(&g_sum_n[cur * ND + c], acc);
}

__global__ void k_pool_edge(const float* __restrict__ he) {
    int e0 = blockIdx.x * 512;
    int c = threadIdx.x;
    float acc = 0.f;
    int cur = -1;
    for (int i = 0; i < 512; i++) {
        int e = e0 + i;
        if (e >= EE) break;
        int b = g_be[e];
        if (b != cur) {
            if (cur >= 0) atomicAdd(&g_sum_e[cur * ED + c], acc);
            cur = b; acc = 0.f;
        }
        acc += he[(size_t)e * ED + c];
    }
    if (cur >= 0) atomicAdd(&g_sum_e[cur * ED + c], acc);
}

__global__ void k_hsub() {
    int idx = blockIdx.x * 256 + threadIdx.x;
    if (idx >= BB * (ND + ED)) return;
    int b = idx / (ND + ED);
    int c = idx % (ND + ED);
    float v;
    if (c < ND) v = g_sum_n[b * ND + c] / fmaxf(g_cnt_n[b], 1.f);
    else        v = g_sum_e[b * ED + (c - ND)] / fmaxf(g_cnt_e[b], 1.f);
    g_hsub[idx] = v;
}

__global__ void k_copy_batch(float* __restrict__ outp) {
    int i = blockIdx.x * 256 + threadIdx.x;
    if (i < NN) outp[i] = (float)g_bn[i];
}

// ------------------------- launch -------------------------
extern "C" void kernel_launch(void* const* d_in, const int* in_sizes, int n_in,
                              void* d_out, int out_size) {
    const float* h_node = (const float*)d_in[0];
    const float* pos    = (const float*)d_in[1];
    const float* h_edge = (const float*)d_in[2];
    const float* W_node = (const float*)d_in[3];
    const float* W_edge = (const float*)d_in[4];
    const float* W_eu   = (const float*)d_in[5];
    const float* b_eu   = (const float*)d_in[6];
    const float* W_msg  = (const float*)d_in[7];
    const float* b_msg  = (const float*)d_in[8];
    const float* W_nu   = (const float*)d_in[9];
    const float* b_nu   = (const float*)d_in[10];
    const float* Wf1    = (const float*)d_in[11];
    const float* bf1    = (const float*)d_in[12];
    const float* Wf2    = (const float*)d_in[13];
    const float* bf2    = (const float*)d_in[14];
    const void*  ei     = d_in[15];
    const void*  bn     = d_in[16];
    const void*  be     = d_in[17];
    float* outp = (float*)d_out;

    float *hn0, *hn1, *he0, *he1, *agg, *Up, *Mp, *Wsd, *distp;
    float *sumn, *sume, *cntn, *cnte, *hsub, *h1;
    int *srcp, *dstp, *bnp, *bep;
    cudaGetSymbolAddress((void**)&hn0, g_hn0);
    cudaGetSymbolAddress((void**)&hn1, g_hn1);
    cudaGetSymbolAddress((void**)&he0, g_he0);
    cudaGetSymbolAddress((void**)&he1, g_he1);
    cudaGetSymbolAddress((void**)&agg, g_agg);
    cudaGetSymbolAddress((void**)&Up,  g_U);
    cudaGetSymbolAddress((void**)&Mp,  g_Msrc);
    cudaGetSymbolAddress((void**)&Wsd, g_Wsd);
    cudaGetSymbolAddress((void**)&distp, g_dist);
    cudaGetSymbolAddress((void**)&srcp, g_src);
    cudaGetSymbolAddress((void**)&dstp, g_dst);
    cudaGetSymbolAddress((void**)&bnp, g_bn);
    cudaGetSymbolAddress((void**)&bep, g_be);
    cudaGetSymbolAddress((void**)&sumn, g_sum_n);
    cudaGetSymbolAddress((void**)&sume, g_sum_e);
    cudaGetSymbolAddress((void**)&cntn, g_cnt_n);
    cudaGetSymbolAddress((void**)&cnte, g_cnt_e);
    cudaGetSymbolAddress((void**)&hsub, g_hsub);
    cudaGetSymbolAddress((void**)&h1, g_h1);

    // normalize index dtypes
    k_detect<<<1, 32>>>((const unsigned int*)ei);
    k_cvt_off<<<(EE + 255) / 256, 256>>>(ei, EE, 0,  srcp);
    k_cvt_off<<<(EE + 255) / 256, 256>>>(ei, EE, EE, dstp);
    k_cvt_off<<<(NN + 255) / 256, 256>>>(bn, NN, 0,  bnp);
    k_cvt_off<<<(EE + 255) / 256, 256>>>(be, EE, 0,  bep);

    k_prep_edge<<<(EE + 255) / 256, 256>>>(pos);
    k_embed_node<<<(NN + 7) / 8, 256>>>(h_node, W_node, hn0);
    k_embed_edge<<<EE / 16, 256>>>(h_edge, W_edge, he0);

    float *hnc = hn0, *hnn = hn1, *hec = he0, *hen = he1;
    for (int l = 0; l < LBLK; l++) {
        const float* Weu_l  = W_eu  + (size_t)l * 641 * 128;
        const float* Wmsg_l = W_msg + (size_t)l * 384 * 256;
        const float* Wnu_l  = W_nu  + (size_t)l * 512 * 256;

        // node-side precomputes
        k_pack_wsd<<<256, 256>>>(Weu_l);
        gemm_k<5><<<dim3((NN + 127) / 128, 2), 256>>>(hnc, nullptr, Wsd, nullptr,
            Up, nullptr, nullptr, nullptr, nullptr, nullptr, nullptr, NN, 256, 256);
        gemm_k<5><<<dim3((NN + 127) / 128, 2), 256>>>(hnc, nullptr, Wmsg_l, nullptr,
            Mp, nullptr, nullptr, nullptr, nullptr, nullptr, nullptr, NN, 256, 256);
        k_zero<<<4096, 256>>>(agg, NN * ND);

        // edge update: he_new = relu(he@W_he + U[src|dst] + dist*wdist + b)
        gemm_k<0><<<dim3(EE / 128, 1), 256>>>(hec, nullptr, Weu_l, b_eu + l * 128,
            hen, nullptr, srcp, dstp, distp, Up, Weu_l + 640 * 128, EE, 128, 128);

        // messages: relu(he_new@W_bot + Msrc[src] + b) scatter-> agg[dst]
        gemm_k<1><<<dim3(EE / 128, 2), 256>>>(hen, nullptr, Wmsg_l + 256 * 256,
            b_msg + l * 256, agg, nullptr, srcp, dstp, nullptr, Mp, nullptr, EE, 128, 256);

        // node update: hn = hn + relu([hn|agg]@W_nu + b)
        gemm_k<2><<<dim3((NN + 127) / 128, 2), 256>>>(hnc, agg, Wnu_l, b_nu + l * 256,
            hnn, hnc, nullptr, nullptr, nullptr, nullptr, nullptr, NN, 512, 256);

        { float* tp = hnc; hnc = hnn; hnn = tp; }
        { float* tp = hec; hec = hen; hen = tp; }
    }

    // pooling
    k_zero<<<256, 256>>>(sumn, BB * ND);
    k_zero<<<256, 256>>>(sume, BB * ED);
    k_zero<<<8, 256>>>(cntn, BB);
    k_zero<<<8, 256>>>(cnte, BB);
    k_count<<<(NN + 255) / 256, 256>>>(bnp, NN, cntn);
    k_count<<<(EE + 255) / 256, 256>>>(bep, EE, cnte);
    k_pool_node<<<(NN + 127) / 128, 256>>>(hnc);
    k_pool_edge<<<(EE + 511) / 512, 128>>>(hec);
    k_hsub<<<(BB * (ND + ED) + 255) / 256, 256>>>();

    // final MLP
    gemm_k<3><<<dim3((BB + 127) / 128, 4), 256>>>(hsub, nullptr, Wf1, bf1,
        h1, nullptr, nullptr, nullptr, nullptr, nullptr, nullptr, BB, 384, 512);
    gemm_k<4><<<dim3((BB + 127) / 128, 2), 256>>>(h1, nullptr, Wf2, bf2,
        outp, nullptr, nullptr, nullptr, nullptr, nullptr, nullptr, BB, 512, 256);

    if (out_size >= BB * EMBD + NN) {
        k_copy_batch<<<(NN + 255) / 256, 256>>>(outp + BB * EMBD);
    }
}

// round 13
// speedup vs baseline: 2.4283x; 2.4283x over previous
#include <cuda_runtime.h>
#include <math.h>
#include <stdint.h>

#define NN 100000
#define EE 640000
#define BB 2000
#define ND 256
#define ED 128
#define EMBD 256
#define LBLK 3

// ------------------------- scratch (no allocations allowed) -------------------------
__device__ float g_hn0[NN * ND];
__device__ float g_hn1[NN * ND];
__device__ float g_he0[EE * ED];
__device__ float g_he1[EE * ED];
__device__ float g_agg[NN * ND];
__device__ float g_U[NN * 256];       // [U_src | U_dst] per node
__device__ float g_Msrc[NN * 256];    // hn @ W_msg_top per node
__device__ float g_Wsd[256 * 256];    // packed [Ws | Wd]
__device__ float g_dist[EE];
__device__ int   g_src[EE];
__device__ int   g_dst[EE];
__device__ int   g_bn[NN];
__device__ int   g_be[EE];
__device__ int   g_is64;
__device__ float g_sum_n[BB * ND];
__device__ float g_sum_e[BB * ED];
__device__ float g_cnt_n[BB];
__device__ float g_cnt_e[BB];
__device__ float g_hsub[BB * (ND + ED)];
__device__ float g_h1[BB * 2 * EMBD];

// ------------------------- f32x2 helpers -------------------------
__device__ __forceinline__ unsigned long long pack_dup(float a) {
    unsigned long long r;
    asm("mov.b64 %0, {%1, %1};" : "=l"(r) : "f"(a));
    return r;
}
__device__ __forceinline__ void unpack2(unsigned long long v, float& lo, float& hi) {
    asm("mov.b64 {%0, %1}, %2;" : "=f"(lo), "=f"(hi) : "l"(v));
}
#define FMA2(acc, a, b) \
    asm("fma.rn.f32x2 %0, %1, %2, %0;" : "+l"(acc) : "l"(a), "l"(b))
#define LDS_V2U64(x, y, addr) \
    asm("ld.shared.v2.u64 {%0, %1}, [%2];" : "=l"(x), "=l"(y) : "r"(addr))

__device__ __forceinline__ uint32_t smem_u32(const void* p) {
    uint32_t a;
    asm("{ .reg .u64 t; cvta.to.shared.u64 t, %1; cvt.u32.u64 %0, t; }" : "=r"(a) : "l"(p));
    return a;
}

// ------------------------- dtype detection (int32 vs int64 indices) -------------------------
__global__ void k_detect(const unsigned int* __restrict__ u) {
    if (threadIdx.x != 0 || blockIdx.x != 0) return;
    int odd_nonzero = 0;
    for (int i = 0; i < 64; i++)
        if (u[2 * i + 1] != 0u) odd_nonzero++;
    g_is64 = (odd_nonzero == 0) ? 1 : 0;
}

__global__ void k_cvt_off(const void* __restrict__ p, int n, int off,
                          int* __restrict__ outp) {
    int i = blockIdx.x * 256 + threadIdx.x;
    if (i >= n) return;
    if (g_is64) outp[i] = (int)((const long long*)p)[off + i];
    else        outp[i] = ((const int*)p)[off + i];
}

// ------------------------- prep -------------------------
__global__ void k_prep_edge(const float* __restrict__ pos) {
    int e = blockIdx.x * 256 + threadIdx.x;
    if (e >= EE) return;
    int s = g_src[e], d = g_dst[e];
    float dx = pos[d * 3 + 0] - pos[s * 3 + 0];
    float dy = pos[d * 3 + 1] - pos[s * 3 + 1];
    float dz = pos[d * 3 + 2] - pos[s * 3 + 2];
    g_dist[e] = sqrtf(dx * dx + dy * dy + dz * dz);
}

// pack W_sd[k][0:128] = W_eu[128+k][:], W_sd[k][128:256] = W_eu[384+k][:]
__global__ void k_pack_wsd(const float* __restrict__ Weu) {
    int i = blockIdx.x * 256 + threadIdx.x;
    if (i >= 256 * 256) return;
    int k = i >> 8, j = i & 255;
    float v = (j < 128) ? Weu[(128 + k) * 128 + j] : Weu[(384 + k) * 128 + (j - 128)];
    g_Wsd[i] = v;
}

// ------------------------- embeddings -------------------------
__global__ void k_embed_node(const float* __restrict__ hfeat,
                             const float* __restrict__ W,
                             float* __restrict__ outp) {
    __shared__ float sw[16 * 256];
    for (int i = threadIdx.x; i < 16 * 256; i += 256) sw[i] = W[i];
    __syncthreads();
    int c = threadIdx.x;
    int n0 = blockIdx.x * 8;
    for (int r = 0; r < 8; r++) {
        int n = n0 + r;
        if (n >= NN) return;
        float acc = 0.f;
#pragma unroll
        for (int k = 0; k < 16; k++) acc += hfeat[n * 16 + k] * sw[k * 256 + c];
        outp[(size_t)n * 256 + c] = acc;
    }
}

__global__ void k_embed_edge(const float* __restrict__ hfeat,
                             const float* __restrict__ W,
                             float* __restrict__ outp) {
    __shared__ float sw[5 * 128];
    for (int i = threadIdx.x; i < 5 * 128; i += 256) sw[i] = W[i];
    __syncthreads();
    int sub = threadIdx.x >> 7;
    int c   = threadIdx.x & 127;
    int e0  = blockIdx.x * 16 + sub;
    for (int r = 0; r < 16; r += 2) {
        int e = e0 + r;
        if (e >= EE) return;
        float acc = 0.f;
#pragma unroll
        for (int k = 0; k < 5; k++) acc += hfeat[e * 5 + k] * sw[k * 128 + c];
        outp[(size_t)e * 128 + c] = acc;
    }
}

// ------------------------- zero -------------------------
__global__ void k_zero(float* __restrict__ p, int n) {
    int i = blockIdx.x * blockDim.x + threadIdx.x;
    int str = gridDim.x * blockDim.x;
    for (; i < n; i += str) p[i] = 0.f;
}

// ---------- tiled SGEMM: FFMA2, row-paired accumulators, R10-identical SMEM layout ----------
// MODE 0 (edge):  A=he[E,128] K=128 N=128; epi: relu(acc+b+U[src][c]+U[dst][128+c]+dist*wdist[c])
// MODE 1 (msg):   A=he_new[E,128] K=128 N=256; epi: relu(acc+b+Msrc[src][c]) -> red.add agg[dst]
// MODE 2 (node):  A=[hn|agg] K=512 N=256; epi: hn + relu(acc+b)
// MODE 3 (mlp1):  A generic; relu(acc+b)
// MODE 4 (mlp2):  A generic; acc+b
// MODE 5 (plain): A generic; acc (no bias)
template <int MODE>
__global__ __launch_bounds__(256) void gemm_k(
    const float* __restrict__ P0, const float* __restrict__ P1,
    const float* __restrict__ Wb, const float* __restrict__ bias,
    float* __restrict__ Cout, const float* __restrict__ Extra,
    const int* __restrict__ src, const int* __restrict__ dst,
    const float* __restrict__ distv, const float* __restrict__ G,
    const float* __restrict__ wdist,
    int Mrows, int Kdim, int Ncols)
{
    __shared__ __align__(16) float As[16][128];
    __shared__ __align__(16) float Bs[16][128];
    const int tid = threadIdx.x;
    const int tx = tid & 15, ty = tid >> 4;
    const int m0 = blockIdx.x * 128;
    const int n0 = blockIdx.y * 128;

    const uint32_t asb = smem_u32(As);
    const uint32_t aAddr0 = asb + (uint32_t)ty * 32;   // 8 floats at As[kk][ty*8]; +kk*512

    // acc2[i][j]: packed pair {row ty*8+2i, row ty*8+2i+1} at col tx*8+j
    unsigned long long acc2[4][8];
#pragma unroll
    for (int i = 0; i < 4; i++)
#pragma unroll
        for (int j = 0; j < 8; j++) acc2[i][j] = 0ull;

    const int ar  = tid & 127;
    const int ak0 = (tid >> 7) * 8;
    const int rowg = m0 + ar;
    const bool rvalid = (rowg < Mrows);

    const int KT = Kdim >> 4;            // all K are multiples of 16
    for (int kt = 0; kt < KT; kt++) {
        // ---- A tile: contiguous 8-float run per thread (R10 layout) ----
        {
            const int k0 = kt * 16 + ak0;
            float4 v0 = make_float4(0.f, 0.f, 0.f, 0.f);
            float4 v1 = v0;
            if (rvalid) {
                const float* ap;
                if (MODE == 0 || MODE == 1)      ap = P0 + (size_t)rowg * 128 + k0;
                else if (MODE == 2)              ap = (k0 < 256) ? P0 + (size_t)rowg * 256 + k0
                                                                : P1 + (size_t)rowg * 256 + (k0 - 256);
                else                             ap = P0 + (size_t)rowg * Kdim + k0;
                v0 = *(const float4*)ap;
                v1 = *(const float4*)(ap + 4);
            }
            As[ak0 + 0][ar] = v0.x; As[ak0 + 1][ar] = v0.y;
            As[ak0 + 2][ar] = v0.z; As[ak0 + 3][ar] = v0.w;
            As[ak0 + 4][ar] = v1.x; As[ak0 + 5][ar] = v1.y;
            As[ak0 + 6][ar] = v1.z; As[ak0 + 7][ar] = v1.w;
        }
        // ---- B tile (R10 layout, coalesced float4) ----
#pragma unroll
        for (int r = 0; r < 2; r++) {
            int f  = tid + r * 256;
            int bk = f >> 5;
            int bc = (f & 31) * 4;
            int kg = kt * 16 + bk;
            *(float4*)&Bs[bk][bc] = *(const float4*)(Wb + (size_t)kg * Ncols + n0 + bc);
        }
        __syncthreads();
#pragma unroll
        for (int kk = 0; kk < 16; kk++) {
            const uint32_t aA = aAddr0 + (uint32_t)kk * 512;
            unsigned long long a2[4];
            LDS_V2U64(a2[0], a2[1], aA);          // rows ty*8+0..3 as 2 pairs
            LDS_V2U64(a2[2], a2[3], aA + 16);     // rows ty*8+4..7 as 2 pairs
            float b[8];
            *(float4*)&b[0] = *(const float4*)&Bs[kk][tx * 8];
            *(float4*)&b[4] = *(const float4*)&Bs[kk][tx * 8 + 4];
            unsigned long long bd[8];
#pragma unroll
            for (int j = 0; j < 8; j++) bd[j] = pack_dup(b[j]);
#pragma unroll
            for (int i = 0; i < 4; i++)
#pragma unroll
                for (int j = 0; j < 8; j++) FMA2(acc2[i][j], a2[i], bd[j]);
        }
        __syncthreads();
    }

    // ---- epilogue ----
    const int cg0 = n0 + tx * 8;
    float bia[8], wd[8];
    if (MODE != 5) {
        *(float4*)&bia[0] = *(const float4*)(bias + cg0);
        *(float4*)&bia[4] = *(const float4*)(bias + cg0 + 4);
    }
    if (MODE == 0) {
        *(float4*)&wd[0] = *(const float4*)(wdist + cg0);
        *(float4*)&wd[4] = *(const float4*)(wdist + cg0 + 4);
    }

#pragma unroll
    for (int i = 0; i < 4; i++) {
        float vp[2][8];
#pragma unroll
        for (int j = 0; j < 8; j++) unpack2(acc2[i][j], vp[0][j], vp[1][j]);
#pragma unroll
        for (int p = 0; p < 2; p++) {
            int rg = m0 + ty * 8 + i * 2 + p;
            if (rg >= Mrows) continue;
            float* accr = vp[p];
            float vals[8];
            if (MODE == 0) {
                int sg = src[rg], dg = dst[rg];
                float dv = distv[rg];
                float gs[8], gd[8];
                *(float4*)&gs[0] = *(const float4*)(G + (size_t)sg * 256 + cg0);
                *(float4*)&gs[4] = *(const float4*)(G + (size_t)sg * 256 + cg0 + 4);
                *(float4*)&gd[0] = *(const float4*)(G + (size_t)dg * 256 + 128 + cg0);
                *(float4*)&gd[4] = *(const float4*)(G + (size_t)dg * 256 + 128 + cg0 + 4);
#pragma unroll
                for (int j = 0; j < 8; j++)
                    vals[j] = fmaxf(accr[j] + bia[j] + gs[j] + gd[j] + dv * wd[j], 0.f);
                *(float4*)(Cout + (size_t)rg * 128 + cg0)     = *(float4*)&vals[0];
                *(float4*)(Cout + (size_t)rg * 128 + cg0 + 4) = *(float4*)&vals[4];
            } else if (MODE == 1) {
                int sg = src[rg], dg = dst[rg];
                float gs[8];
                *(float4*)&gs[0] = *(const float4*)(G + (size_t)sg * 256 + cg0);
                *(float4*)&gs[4] = *(const float4*)(G + (size_t)sg * 256 + cg0 + 4);
#pragma unroll
                for (int j = 0; j < 8; j++)
                    vals[j] = fmaxf(accr[j] + bia[j] + gs[j], 0.f);
                float* ap = Cout + (size_t)dg * 256 + cg0;
                asm volatile("red.global.add.v4.f32 [%0], {%1,%2,%3,%4};"
                             :: "l"(ap), "f"(vals[0]), "f"(vals[1]), "f"(vals[2]), "f"(vals[3])
                             : "memory");
                asm volatile("red.global.add.v4.f32 [%0], {%1,%2,%3,%4};"
                             :: "l"(ap + 4), "f"(vals[4]), "f"(vals[5]), "f"(vals[6]), "f"(vals[7])
                             : "memory");
            } else if (MODE == 2) {
                float ex[8];
                *(float4*)&ex[0] = *(const float4*)(Extra + (size_t)rg * 256 + cg0);
                *(float4*)&ex[4] = *(const float4*)(Extra + (size_t)rg * 256 + cg0 + 4);
#pragma unroll
                for (int j = 0; j < 8; j++)
                    vals[j] = ex[j] + fmaxf(accr[j] + bia[j], 0.f);
                *(float4*)(Cout + (size_t)rg * 256 + cg0)     = *(float4*)&vals[0];
                *(float4*)(Cout + (size_t)rg * 256 + cg0 + 4) = *(float4*)&vals[4];
            } else {
#pragma unroll
                for (int j = 0; j < 8; j++) {
                    float v = accr[j] + (MODE == 5 ? 0.f : bia[j]);
                    if (MODE == 3) v = fmaxf(v, 0.f);
                    vals[j] = v;
                }
                *(float4*)(Cout + (size_t)rg * Ncols + cg0)     = *(float4*)&vals[0];
                *(float4*)(Cout + (size_t)rg * Ncols + cg0 + 4) = *(float4*)&vals[4];
            }
        }
    }
}

// ------------------------- pooling -------------------------
__global__ void k_count(const int* __restrict__ b, int n, float* __restrict__ cnt) {
    int i = blockIdx.x * 256 + threadIdx.x;
    if (i < n) atomicAdd(&cnt[b[i]], 1.f);
}

__global__ void k_pool_node(const float* __restrict__ hn) {
    int n0 = blockIdx.x * 128;
    int c = threadIdx.x;
    float acc = 0.f;
    int cur = -1;
    for (int i = 0; i < 128; i++) {
        int n = n0 + i;
        if (n >= NN) break;
        int b = g_bn[n];
        if (b != cur) {
            if (cur >= 0) atomicAdd(&g_sum_n[cur * ND + c], acc);
            cur = b; acc = 0.f;
        }
        acc += hn[(size_t)n * ND + c];
    }
    if (cur >= 0) atomicAdd(&g_sum_n[cur * ND + c], acc);
}

__global__ void k_pool_edge(const float* __restrict__ he) {
    int e0 = blockIdx.x * 512;
    int c = threadIdx.x;
    float acc = 0.f;
    int cur = -1;
    for (int i = 0; i < 512; i++) {
        int e = e0 + i;
        if (e >= EE) break;
        int b = g_be[e];
        if (b != cur) {
            if (cur >= 0) atomicAdd(&g_sum_e[cur * ED + c], acc);
            cur = b; acc = 0.f;
        }
        acc += he[(size_t)e * ED + c];
    }
    if (cur >= 0) atomicAdd(&g_sum_e[cur * ED + c], acc);
}

__global__ void k_hsub() {
    int idx = blockIdx.x * 256 + threadIdx.x;
    if (idx >= BB * (ND + ED)) return;
    int b = idx / (ND + ED);
    int c = idx % (ND + ED);
    float v;
    if (c < ND) v = g_sum_n[b * ND + c] / fmaxf(g_cnt_n[b], 1.f);
    else        v = g_sum_e[b * ED + (c - ND)] / fmaxf(g_cnt_e[b], 1.f);
    g_hsub[idx] = v;
}

__global__ void k_copy_batch(float* __restrict__ outp) {
    int i = blockIdx.x * 256 + threadIdx.x;
    if (i < NN) outp[i] = (float)g_bn[i];
}

// ------------------------- launch -------------------------
extern "C" void kernel_launch(void* const* d_in, const int* in_sizes, int n_in,
                              void* d_out, int out_size) {
    const float* h_node = (const float*)d_in[0];
    const float* pos    = (const float*)d_in[1];
    const float* h_edge = (const float*)d_in[2];
    const float* W_node = (const float*)d_in[3];
    const float* W_edge = (const float*)d_in[4];
    const float* W_eu   = (const float*)d_in[5];
    const float* b_eu   = (const float*)d_in[6];
    const float* W_msg  = (const float*)d_in[7];
    const float* b_msg  = (const float*)d_in[8];
    const float* W_nu   = (const float*)d_in[9];
    const float* b_nu   = (const float*)d_in[10];
    const float* Wf1    = (const float*)d_in[11];
    const float* bf1    = (const float*)d_in[12];
    const float* Wf2    = (const float*)d_in[13];
    const float* bf2    = (const float*)d_in[14];
    const void*  ei     = d_in[15];
    const void*  bn     = d_in[16];
    const void*  be     = d_in[17];
    float* outp = (float*)d_out;

    float *hn0, *hn1, *he0, *he1, *agg, *Up, *Mp, *Wsd, *distp;
    float *sumn, *sume, *cntn, *cnte, *hsub, *h1;
    int *srcp, *dstp, *bnp, *bep;
    cudaGetSymbolAddress((void**)&hn0, g_hn0);
    cudaGetSymbolAddress((void**)&hn1, g_hn1);
    cudaGetSymbolAddress((void**)&he0, g_he0);
    cudaGetSymbolAddress((void**)&he1, g_he1);
    cudaGetSymbolAddress((void**)&agg, g_agg);
    cudaGetSymbolAddress((void**)&Up,  g_U);
    cudaGetSymbolAddress((void**)&Mp,  g_Msrc);
    cudaGetSymbolAddress((void**)&Wsd, g_Wsd);
    cudaGetSymbolAddress((void**)&distp, g_dist);
    cudaGetSymbolAddress((void**)&srcp, g_src);
    cudaGetSymbolAddress((void**)&dstp, g_dst);
    cudaGetSymbolAddress((void**)&bnp, g_bn);
    cudaGetSymbolAddress((void**)&bep, g_be);
    cudaGetSymbolAddress((void**)&sumn, g_sum_n);
    cudaGetSymbolAddress((void**)&sume, g_sum_e);
    cudaGetSymbolAddress((void**)&cntn, g_cnt_n);
    cudaGetSymbolAddress((void**)&cnte, g_cnt_e);
    cudaGetSymbolAddress((void**)&hsub, g_hsub);
    cudaGetSymbolAddress((void**)&h1, g_h1);

    // normalize index dtypes
    k_detect<<<1, 32>>>((const unsigned int*)ei);
    k_cvt_off<<<(EE + 255) / 256, 256>>>(ei, EE, 0,  srcp);
    k_cvt_off<<<(EE + 255) / 256, 256>>>(ei, EE, EE, dstp);
    k_cvt_off<<<(NN + 255) / 256, 256>>>(bn, NN, 0,  bnp);
    k_cvt_off<<<(EE + 255) / 256, 256>>>(be, EE, 0,  bep);

    k_prep_edge<<<(EE + 255) / 256, 256>>>(pos);
    k_embed_node<<<(NN + 7) / 8, 256>>>(h_node, W_node, hn0);
    k_embed_edge<<<EE / 16, 256>>>(h_edge, W_edge, he0);

    float *hnc = hn0, *hnn = hn1, *hec = he0, *hen = he1;
    for (int l = 0; l < LBLK; l++) {
        const float* Weu_l  = W_eu  + (size_t)l * 641 * 128;
        const float* Wmsg_l = W_msg + (size_t)l * 384 * 256;
        const float* Wnu_l  = W_nu  + (size_t)l * 512 * 256;

        // node-side precomputes
        k_pack_wsd<<<256, 256>>>(Weu_l);
        gemm_k<5><<<dim3((NN + 127) / 128, 2), 256>>>(hnc, nullptr, Wsd, nullptr,
            Up, nullptr, nullptr, nullptr, nullptr, nullptr, nullptr, NN, 256, 256);
        gemm_k<5><<<dim3((NN + 127) / 128, 2), 256>>>(hnc, nullptr, Wmsg_l, nullptr,
            Mp, nullptr, nullptr, nullptr, nullptr, nullptr, nullptr, NN, 256, 256);
        k_zero<<<4096, 256>>>(agg, NN * ND);

        // edge update: he_new = relu(he@W_he + U[src|dst] + dist*wdist + b)
        gemm_k<0><<<dim3(EE / 128, 1), 256>>>(hec, nullptr, Weu_l, b_eu + l * 128,
            hen, nullptr, srcp, dstp, distp, Up, Weu_l + 640 * 128, EE, 128, 128);

        // messages: relu(he_new@W_bot + Msrc[src] + b) scatter-> agg[dst]
        gemm_k<1><<<dim3(EE / 128, 2), 256>>>(hen, nullptr, Wmsg_l + 256 * 256,
            b_msg + l * 256, agg, nullptr, srcp, dstp, nullptr, Mp, nullptr, EE, 128, 256);

        // node update: hn = hn + relu([hn|agg]@W_nu + b)
        gemm_k<2><<<dim3((NN + 127) / 128, 2), 256>>>(hnc, agg, Wnu_l, b_nu + l * 256,
            hnn, hnc, nullptr, nullptr, nullptr, nullptr, nullptr, NN, 512, 256);

        { float* tp = hnc; hnc = hnn; hnn = tp; }
        { float* tp = hec; hec = hen; hen = tp; }
    }

    // pooling
    k_zero<<<256, 256>>>(sumn, BB * ND);
    k_zero<<<256, 256>>>(sume, BB * ED);
    k_zero<<<8, 256>>>(cntn, BB);
    k_zero<<<8, 256>>>(cnte, BB);
    k_count<<<(NN + 255) / 256, 256>>>(bnp, NN, cntn);
    k_count<<<(EE + 255) / 256, 256>>>(bep, EE, cnte);
    k_pool_node<<<(NN + 127) / 128, 256>>>(hnc);
    k_pool_edge<<<(EE + 511) / 512, 128>>>(hec);
    k_hsub<<<(BB * (ND + ED) + 255) / 256, 256>>>();

    // final MLP
    gemm_k<3><<<dim3((BB + 127) / 128, 4), 256>>>(hsub, nullptr, Wf1, bf1,
        h1, nullptr, nullptr, nullptr, nullptr, nullptr, nullptr, BB, 384, 512);
    gemm_k<4><<<dim3((BB + 127) / 128, 2), 256>>>(h1, nullptr, Wf2, bf2,
        outp, nullptr, nullptr, nullptr, nullptr, nullptr, nullptr, BB, 512, 256);

    if (out_size >= BB * EMBD + NN) {
        k_copy_batch<<<(NN + 255) / 256, 256>>>(outp + BB * EMBD);
    }
}

// round 16
// speedup vs baseline: 2.6843x; 1.1054x over previous
#include <cuda_runtime.h>
#include <math.h>
#include <stdint.h>

#define NN 100000
#define EE 640000
#define BB 2000
#define ND 256
#define ED 128
#define EMBD 256
#define LBLK 3

// ------------------------- scratch (no allocations allowed) -------------------------
__device__ float g_hn0[NN * ND];
__device__ float g_hn1[NN * ND];
__device__ float g_he0[EE * ED];
__device__ float g_he1[EE * ED];
__device__ float g_agg[NN * ND];
__device__ float g_U[NN * 256];        // [U_src | U_dst] per node
__device__ float g_Msrc[NN * 256];     // hn @ W_msg_top per node
__device__ float g_Wsd[256 * 256];     // packed [Ws | Wd]
__device__ float g_hepad[EE * 16];     // h_edge padded to 16 cols
__device__ float g_wcomb[16 * 128];    // W_edge @ W_he   (rows 5..15 zero)
__device__ float g_wsd0[16 * 256];     // W_node @ Wsd
__device__ float g_wmsg0[16 * 256];    // W_node @ Wmsg_top
__device__ float g_dist[EE];
__device__ int   g_src[EE];
__device__ int   g_dst[EE];
__device__ int   g_bn[NN];
__device__ int   g_be[EE];
__device__ int   g_is64;
__device__ float g_sum_n[BB * ND];
__device__ float g_sum_e[BB * ED];
__device__ float g_cnt_n[BB];
__device__ float g_cnt_e[BB];
__device__ float g_hsub[BB * (ND + ED)];
__device__ float g_h1[BB * 2 * EMBD];

// ------------------------- f32x2 helpers -------------------------
__device__ __forceinline__ unsigned long long pack_dup(float a) {
    unsigned long long r;
    asm("mov.b64 %0, {%1, %1};" : "=l"(r) : "f"(a));
    return r;
}
__device__ __forceinline__ void unpack2(unsigned long long v, float& lo, float& hi) {
    asm("mov.b64 {%0, %1}, %2;" : "=f"(lo), "=f"(hi) : "l"(v));
}
#define FMA2(acc, a, b) \
    asm("fma.rn.f32x2 %0, %1, %2, %0;" : "+l"(acc) : "l"(a), "l"(b))
#define LDS_V2U64(x, y, addr) \
    asm("ld.shared.v2.u64 {%0, %1}, [%2];" : "=l"(x), "=l"(y) : "r"(addr))

__device__ __forceinline__ uint32_t smem_u32(const void* p) {
    uint32_t a;
    asm("{ .reg .u64 t; cvta.to.shared.u64 t, %1; cvt.u32.u64 %0, t; }" : "=r"(a) : "l"(p));
    return a;
}

// ------------------------- dtype detection (int32 vs int64 indices) -------------------------
__global__ void k_detect(const unsigned int* __restrict__ u) {
    if (threadIdx.x != 0 || blockIdx.x != 0) return;
    int odd_nonzero = 0;
    for (int i = 0; i < 64; i++)
        if (u[2 * i + 1] != 0u) odd_nonzero++;
    g_is64 = (odd_nonzero == 0) ? 1 : 0;
}

__global__ void k_cvt_off(const void* __restrict__ p, int n, int off,
                          int* __restrict__ outp) {
    int i = blockIdx.x * 256 + threadIdx.x;
    if (i >= n) return;
    if (g_is64) outp[i] = (int)((const long long*)p)[off + i];
    else        outp[i] = ((const int*)p)[off + i];
}

// ------------------------- prep -------------------------
__global__ void k_prep_edge(const float* __restrict__ pos) {
    int e = blockIdx.x * 256 + threadIdx.x;
    if (e >= EE) return;
    int s = g_src[e], d = g_dst[e];
    float dx = pos[d * 3 + 0] - pos[s * 3 + 0];
    float dy = pos[d * 3 + 1] - pos[s * 3 + 1];
    float dz = pos[d * 3 + 2] - pos[s * 3 + 2];
    g_dist[e] = sqrtf(dx * dx + dy * dy + dz * dz);
}

// pack W_sd[k][0:128] = W_eu[128+k][:], W_sd[k][128:256] = W_eu[384+k][:]
__global__ void k_pack_wsd(const float* __restrict__ Weu) {
    int i = blockIdx.x * 256 + threadIdx.x;
    if (i >= 256 * 256) return;
    int k = i >> 8, j = i & 255;
    float v = (j < 128) ? Weu[(128 + k) * 128 + j] : Weu[(384 + k) * 128 + (j - 128)];
    g_Wsd[i] = v;
}

// pad h_edge [E,5] -> [E,16] (cols 5..15 zero)
__global__ void k_pad_edge(const float* __restrict__ hfeat) {
    int i = blockIdx.x * 256 + threadIdx.x;
    if (i >= EE * 16) return;
    int e = i >> 4, c = i & 15;
    g_hepad[i] = (c < 5) ? hfeat[e * 5 + c] : 0.f;
}

// ------------------------- node embedding (hn0 still needed for layers>=1 + MODE2) ----
__global__ void k_embed_node(const float* __restrict__ hfeat,
                             const float* __restrict__ W,
                             float* __restrict__ outp) {
    __shared__ float sw[16 * 256];
    for (int i = threadIdx.x; i < 16 * 256; i += 256) sw[i] = W[i];
    __syncthreads();
    int c = threadIdx.x;
    int n0 = blockIdx.x * 8;
    for (int r = 0; r < 8; r++) {
        int n = n0 + r;
        if (n >= NN) return;
        float acc = 0.f;
#pragma unroll
        for (int k = 0; k < 16; k++) acc += hfeat[n * 16 + k] * sw[k * 256 + c];
        outp[(size_t)n * 256 + c] = acc;
    }
}

// ------------------------- zero -------------------------
__global__ void k_zero(float* __restrict__ p, int n) {
    int i = blockIdx.x * blockDim.x + threadIdx.x;
    int str = gridDim.x * blockDim.x;
    for (; i < n; i += str) p[i] = 0.f;
}

// ---------- tiled SGEMM: FFMA2, row-paired accumulators ----------
// A row width == Kdim for all modes except MODE 2 (two 256-wide halves).
// MODE 0 (edge):  epi: relu(acc+b+U[src][c]+U[dst][128+c]+dist*wdist[c]) -> Cout stride 128
// MODE 1 (msg):   epi: relu(acc+b+Msrc[src][c]) -> red.add agg[dst] stride 256
// MODE 2 (node):  A=[hn|agg] K=512 N=256; epi: hn + relu(acc+b)
// MODE 3 (mlp1):  relu(acc+b)
// MODE 4 (mlp2):  acc+b
// MODE 5 (plain): acc (no bias)
template <int MODE>
__global__ __launch_bounds__(256) void gemm_k(
    const float* __restrict__ P0, const float* __restrict__ P1,
    const float* __restrict__ Wb, const float* __restrict__ bias,
    float* __restrict__ Cout, const float* __restrict__ Extra,
    const int* __restrict__ src, const int* __restrict__ dst,
    const float* __restrict__ distv, const float* __restrict__ G,
    const float* __restrict__ wdist,
    int Mrows, int Kdim, int Ncols)
{
    __shared__ __align__(16) float As[16][128];
    __shared__ __align__(16) float Bs[16][128];
    const int tid = threadIdx.x;
    const int tx = tid & 15, ty = tid >> 4;
    const int m0 = blockIdx.x * 128;
    const int n0 = blockIdx.y * 128;

    const uint32_t asb = smem_u32(As);
    const uint32_t aAddr0 = asb + (uint32_t)ty * 32;   // 8 floats at As[kk][ty*8]; +kk*512

    // acc2[i][j]: packed pair {row ty*8+2i, row ty*8+2i+1} at col tx*8+j
    unsigned long long acc2[4][8];
#pragma unroll
    for (int i = 0; i < 4; i++)
#pragma unroll
        for (int j = 0; j < 8; j++) acc2[i][j] = 0ull;

    const int ar  = tid & 127;
    const int ak0 = (tid >> 7) * 8;
    const int rowg = m0 + ar;
    const bool rvalid = (rowg < Mrows);

    const int KT = Kdim >> 4;            // all K are multiples of 16
    for (int kt = 0; kt < KT; kt++) {
        // ---- A tile: contiguous 8-float run per thread ----
        {
            const int k0 = kt * 16 + ak0;
            float4 v0 = make_float4(0.f, 0.f, 0.f, 0.f);
            float4 v1 = v0;
            if (rvalid) {
                const float* ap;
                if (MODE == 2) ap = (k0 < 256) ? P0 + (size_t)rowg * 256 + k0
                                               : P1 + (size_t)rowg * 256 + (k0 - 256);
                else           ap = P0 + (size_t)rowg * Kdim + k0;
                v0 = *(const float4*)ap;
                v1 = *(const float4*)(ap + 4);
            }
            As[ak0 + 0][ar] = v0.x; As[ak0 + 1][ar] = v0.y;
            As[ak0 + 2][ar] = v0.z; As[ak0 + 3][ar] = v0.w;
            As[ak0 + 4][ar] = v1.x; As[ak0 + 5][ar] = v1.y;
            As[ak0 + 6][ar] = v1.z; As[ak0 + 7][ar] = v1.w;
        }
        // ---- B tile (coalesced float4) ----
#pragma unroll
        for (int r = 0; r < 2; r++) {
            int f  = tid + r * 256;
            int bk = f >> 5;
            int bc = (f & 31) * 4;
            int kg = kt * 16 + bk;
            *(float4*)&Bs[bk][bc] = *(const float4*)(Wb + (size_t)kg * Ncols + n0 + bc);
        }
        __syncthreads();
#pragma unroll
        for (int kk = 0; kk < 16; kk++) {
            const uint32_t aA = aAddr0 + (uint32_t)kk * 512;
            unsigned long long a2[4];
            LDS_V2U64(a2[0], a2[1], aA);          // rows ty*8+0..3 as 2 pairs
            LDS_V2U64(a2[2], a2[3], aA + 16);     // rows ty*8+4..7 as 2 pairs
            float b[8];
            *(float4*)&b[0] = *(const float4*)&Bs[kk][tx * 8];
            *(float4*)&b[4] = *(const float4*)&Bs[kk][tx * 8 + 4];
            unsigned long long bd[8];
#pragma unroll
            for (int j = 0; j < 8; j++) bd[j] = pack_dup(b[j]);
#pragma unroll
            for (int i = 0; i < 4; i++)
#pragma unroll
                for (int j = 0; j < 8; j++) FMA2(acc2[i][j], a2[i], bd[j]);
        }
        __syncthreads();
    }

    // ---- epilogue ----
    const int cg0 = n0 + tx * 8;
    float bia[8], wd[8];
    if (MODE != 5) {
        *(float4*)&bia[0] = *(const float4*)(bias + cg0);
        *(float4*)&bia[4] = *(const float4*)(bias + cg0 + 4);
    }
    if (MODE == 0) {
        *(float4*)&wd[0] = *(const float4*)(wdist + cg0);
        *(float4*)&wd[4] = *(const float4*)(wdist + cg0 + 4);
    }

#pragma unroll
    for (int i = 0; i < 4; i++) {
        float vp[2][8];
#pragma unroll
        for (int j = 0; j < 8; j++) unpack2(acc2[i][j], vp[0][j], vp[1][j]);
#pragma unroll
        for (int p = 0; p < 2; p++) {
            int rg = m0 + ty * 8 + i * 2 + p;
            if (rg >= Mrows) continue;
            float* accr = vp[p];
            float vals[8];
            if (MODE == 0) {
                int sg = src[rg], dg = dst[rg];
                float dv = distv[rg];
                float gs[8], gd[8];
                *(float4*)&gs[0] = *(const float4*)(G + (size_t)sg * 256 + cg0);
                *(float4*)&gs[4] = *(const float4*)(G + (size_t)sg * 256 + cg0 + 4);
                *(float4*)&gd[0] = *(const float4*)(G + (size_t)dg * 256 + 128 + cg0);
                *(float4*)&gd[4] = *(const float4*)(G + (size_t)dg * 256 + 128 + cg0 + 4);
#pragma unroll
                for (int j = 0; j < 8; j++)
                    vals[j] = fmaxf(accr[j] + bia[j] + gs[j] + gd[j] + dv * wd[j], 0.f);
                *(float4*)(Cout + (size_t)rg * 128 + cg0)     = *(float4*)&vals[0];
                *(float4*)(Cout + (size_t)rg * 128 + cg0 + 4) = *(float4*)&vals[4];
            } else if (MODE == 1) {
                int sg = src[rg], dg = dst[rg];
                float gs[8];
                *(float4*)&gs[0] = *(const float4*)(G + (size_t)sg * 256 + cg0);
                *(float4*)&gs[4] = *(const float4*)(G + (size_t)sg * 256 + cg0 + 4);
#pragma unroll
                for (int j = 0; j < 8; j++)
                    vals[j] = fmaxf(accr[j] + bia[j] + gs[j], 0.f);
                float* ap = Cout + (size_t)dg * 256 + cg0;
                asm volatile("red.global.add.v4.f32 [%0], {%1,%2,%3,%4};"
                             :: "l"(ap), "f"(vals[0]), "f"(vals[1]), "f"(vals[2]), "f"(vals[3])
                             : "memory");
                asm volatile("red.global.add.v4.f32 [%0], {%1,%2,%3,%4};"
                             :: "l"(ap + 4), "f"(vals[4]), "f"(vals[5]), "f"(vals[6]), "f"(vals[7])
                             : "memory");
            } else if (MODE == 2) {
                float ex[8];
                *(float4*)&ex[0] = *(const float4*)(Extra + (size_t)rg * 256 + cg0);
                *(float4*)&ex[4] = *(const float4*)(Extra + (size_t)rg * 256 + cg0 + 4);
#pragma unroll
                for (int j = 0; j < 8; j++)
                    vals[j] = ex[j] + fmaxf(accr[j] + bia[j], 0.f);
                *(float4*)(Cout + (size_t)rg * 256 + cg0)     = *(float4*)&vals[0];
                *(float4*)(Cout + (size_t)rg * 256 + cg0 + 4) = *(float4*)&vals[4];
            } else {
#pragma unroll
                for (int j = 0; j < 8; j++) {
                    float v = accr[j] + (MODE == 5 ? 0.f : bia[j]);
                    if (MODE == 3) v = fmaxf(v, 0.f);
                    vals[j] = v;
                }
                *(float4*)(Cout + (size_t)rg * Ncols + cg0)     = *(float4*)&vals[0];
                *(float4*)(Cout + (size_t)rg * Ncols + cg0 + 4) = *(float4*)&vals[4];
            }
        }
    }
}

// ------------------------- pooling -------------------------
__global__ void k_count(const int* __restrict__ b, int n, float* __restrict__ cnt) {
    int i = blockIdx.x * 256 + threadIdx.x;
    if (i < n) atomicAdd(&cnt[b[i]], 1.f);
}

__global__ void k_pool_node(const float* __restrict__ hn) {
    int n0 = blockIdx.x * 128;
    int c = threadIdx.x;
    float acc = 0.f;
    int cur = -1;
    for (int i = 0; i < 128; i++) {
        int n = n0 + i;
        if (n >= NN) break;
        int b = g_bn[n];
        if (b != cur) {
            if (cur >= 0) atomicAdd(&g_sum_n[cur * ND + c], acc);
            cur = b; acc = 0.f;
        }
        acc += hn[(size_t)n * ND + c];
    }
    if (cur >= 0) atomicAdd(&g_sum_n[cur * ND + c], acc);
}

__global__ void k_pool_edge(const float* __restrict__ he) {
    int e0 = blockIdx.x * 512;
    int c = threadIdx.x;
    float acc = 0.f;
    int cur = -1;
    for (int i = 0; i < 512; i++) {
        int e = e0 + i;
        if (e >= EE) break;
        int b = g_be[e];
        if (b != cur) {
            if (cur >= 0) atomicAdd(&g_sum_e[cur * ED + c], acc);
            cur = b; acc = 0.f;
        }
        acc += he[(size_t)e * ED + c];
    }
    if (cur >= 0) atomicAdd(&g_sum_e[cur * ED + c], acc);
}

__global__ void k_hsub() {
    int idx = blockIdx.x * 256 + threadIdx.x;
    if (idx >= BB * (ND + ED)) return;
    int b = idx / (ND + ED);
    int c = idx % (ND + ED);
    float v;
    if (c < ND) v = g_sum_n[b * ND + c] / fmaxf(g_cnt_n[b], 1.f);
    else        v = g_sum_e[b * ED + (c - ND)] / fmaxf(g_cnt_e[b], 1.f);
    g_hsub[idx] = v;
}

__global__ void k_copy_batch(float* __restrict__ outp) {
    int i = blockIdx.x * 256 + threadIdx.x;
    if (i < NN) outp[i] = (float)g_bn[i];
}

// ------------------------- launch -------------------------
extern "C" void kernel_launch(void* const* d_in, const int* in_sizes, int n_in,
                              void* d_out, int out_size) {
    const float* h_node = (const float*)d_in[0];
    const float* pos    = (const float*)d_in[1];
    const float* h_edge = (const float*)d_in[2];
    const float* W_node = (const float*)d_in[3];
    const float* W_edge = (const float*)d_in[4];
    const float* W_eu   = (const float*)d_in[5];
    const float* b_eu   = (const float*)d_in[6];
    const float* W_msg  = (const float*)d_in[7];
    const float* b_msg  = (const float*)d_in[8];
    const float* W_nu   = (const float*)d_in[9];
    const float* b_nu   = (const float*)d_in[10];
    const float* Wf1    = (const float*)d_in[11];
    const float* bf1    = (const float*)d_in[12];
    const float* Wf2    = (const float*)d_in[13];
    const float* bf2    = (const float*)d_in[14];
    const void*  ei     = d_in[15];
    const void*  bn     = d_in[16];
    const void*  be     = d_in[17];
    float* outp = (float*)d_out;

    float *hn0, *hn1, *he0, *he1, *agg, *Up, *Mp, *Wsd, *distp;
    float *hepad, *wcomb, *wsd0, *wmsg0;
    float *sumn, *sume, *cntn, *cnte, *hsub, *h1;
    int *srcp, *dstp, *bnp, *bep;
    cudaGetSymbolAddress((void**)&hn0, g_hn0);
    cudaGetSymbolAddress((void**)&hn1, g_hn1);
    cudaGetSymbolAddress((void**)&he0, g_he0);
    cudaGetSymbolAddress((void**)&he1, g_he1);
    cudaGetSymbolAddress((void**)&agg, g_agg);
    cudaGetSymbolAddress((void**)&Up,  g_U);
    cudaGetSymbolAddress((void**)&Mp,  g_Msrc);
    cudaGetSymbolAddress((void**)&Wsd, g_Wsd);
    cudaGetSymbolAddress((void**)&hepad, g_hepad);
    cudaGetSymbolAddress((void**)&wcomb, g_wcomb);
    cudaGetSymbolAddress((void**)&wsd0, g_wsd0);
    cudaGetSymbolAddress((void**)&wmsg0, g_wmsg0);
    cudaGetSymbolAddress((void**)&distp, g_dist);
    cudaGetSymbolAddress((void**)&srcp, g_src);
    cudaGetSymbolAddress((void**)&dstp, g_dst);
    cudaGetSymbolAddress((void**)&bnp, g_bn);
    cudaGetSymbolAddress((void**)&bep, g_be);
    cudaGetSymbolAddress((void**)&sumn, g_sum_n);
    cudaGetSymbolAddress((void**)&sume, g_sum_e);
    cudaGetSymbolAddress((void**)&cntn, g_cnt_n);
    cudaGetSymbolAddress((void**)&cnte, g_cnt_e);
    cudaGetSymbolAddress((void**)&hsub, g_hsub);
    cudaGetSymbolAddress((void**)&h1, g_h1);

    // normalize index dtypes
    k_detect<<<1, 32>>>((const unsigned int*)ei);
    k_cvt_off<<<(EE + 255) / 256, 256>>>(ei, EE, 0,  srcp);
    k_cvt_off<<<(EE + 255) / 256, 256>>>(ei, EE, EE, dstp);
    k_cvt_off<<<(NN + 255) / 256, 256>>>(bn, NN, 0,  bnp);
    k_cvt_off<<<(EE + 255) / 256, 256>>>(be, EE, 0,  bep);

    k_prep_edge<<<(EE + 255) / 256, 256>>>(pos);
    k_embed_node<<<(NN + 7) / 8, 256>>>(h_node, W_node, hn0);
    k_pad_edge<<<(EE * 16 + 255) / 256, 256>>>(h_edge);

    float *hnc = hn0, *hnn = hn1, *hec = he0, *hen = he1;
    for (int l = 0; l < LBLK; l++) {
        const float* Weu_l  = W_eu  + (size_t)l * 641 * 128;
        const float* Wmsg_l = W_msg + (size_t)l * 384 * 256;
        const float* Wnu_l  = W_nu  + (size_t)l * 512 * 256;

        k_pack_wsd<<<256, 256>>>(Weu_l);
        k_zero<<<4096, 256>>>(agg, NN * ND);

        if (l == 0) {
            // tiny composite weights (K folded through the embeddings)
            k_zero<<<8, 256>>>(wcomb, 16 * 128);
            gemm_k<5><<<dim3(1, 2), 256>>>(W_node, nullptr, Wsd, nullptr,
                wsd0, nullptr, nullptr, nullptr, nullptr, nullptr, nullptr, 16, 256, 256);
            gemm_k<5><<<dim3(1, 2), 256>>>(W_node, nullptr, Wmsg_l, nullptr,
                wmsg0, nullptr, nullptr, nullptr, nullptr, nullptr, nullptr, 16, 256, 256);
            gemm_k<5><<<dim3(1, 1), 256>>>(W_edge, nullptr, Weu_l, nullptr,
                wcomb, nullptr, nullptr, nullptr, nullptr, nullptr, nullptr, 5, 128, 128);
            // node-side precomputes at K=16
            gemm_k<5><<<dim3((NN + 127) / 128, 2), 256>>>(h_node, nullptr, wsd0, nullptr,
                Up, nullptr, nullptr, nullptr, nullptr, nullptr, nullptr, NN, 16, 256);
            gemm_k<5><<<dim3((NN + 127) / 128, 2), 256>>>(h_node, nullptr, wmsg0, nullptr,
                Mp, nullptr, nullptr, nullptr, nullptr, nullptr, nullptr, NN, 16, 256);
            // edge update at K=16 (he0 never materialized)
            gemm_k<0><<<dim3(EE / 128, 1), 256>>>(hepad, nullptr, wcomb, b_eu,
                hen, nullptr, srcp, dstp, distp, Up, Weu_l + 640 * 128, EE, 16, 128);
        } else {
            gemm_k<5><<<dim3((NN + 127) / 128, 2), 256>>>(hnc, nullptr, Wsd, nullptr,
                Up, nullptr, nullptr, nullptr, nullptr, nullptr, nullptr, NN, 256, 256);
            gemm_k<5><<<dim3((NN + 127) / 128, 2), 256>>>(hnc, nullptr, Wmsg_l, nullptr,
                Mp, nullptr, nullptr, nullptr, nullptr, nullptr, nullptr, NN, 256, 256);
            gemm_k<0><<<dim3(EE / 128, 1), 256>>>(hec, nullptr, Weu_l, b_eu + l * 128,
                hen, nullptr, srcp, dstp, distp, Up, Weu_l + 640 * 128, EE, 128, 128);
        }

        // messages: relu(he_new@W_bot + Msrc[src] + b) scatter-> agg[dst]
        gemm_k<1><<<dim3(EE / 128, 2), 256>>>(hen, nullptr, Wmsg_l + 256 * 256,
            b_msg + l * 256, agg, nullptr, srcp, dstp, nullptr, Mp, nullptr, EE, 128, 256);

        // node update: hn = hn + relu([hn|agg]@W_nu + b)
        gemm_k<2><<<dim3((NN + 127) / 128, 2), 256>>>(hnc, agg, Wnu_l, b_nu + l * 256,
            hnn, hnc, nullptr, nullptr, nullptr, nullptr, nullptr, NN, 512, 256);

        { float* tp = hnc; hnc = hnn; hnn = tp; }
        { float* tp = hec; hec = hen; hen = tp; }
    }

    // pooling
    k_zero<<<256, 256>>>(sumn, BB * ND);
    k_zero<<<256, 256>>>(sume, BB * ED);
    k_zero<<<8, 256>>>(cntn, BB);
    k_zero<<<8, 256>>>(cnte, BB);
    k_count<<<(NN + 255) / 256, 256>>>(bnp, NN, cntn);
    k_count<<<(EE + 255) / 256, 256>>>(bep, EE, cnte);
    k_pool_node<<<(NN + 127) / 128, 256>>>(hnc);
    k_pool_edge<<<(EE + 511) / 512, 128>>>(hec);
    k_hsub<<<(BB * (ND + ED) + 255) / 256, 256>>>();

    // final MLP
    gemm_k<3><<<dim3((BB + 127) / 128, 4), 256>>>(hsub, nullptr, Wf1, bf1,
        h1, nullptr, nullptr, nullptr, nullptr, nullptr, nullptr, BB, 384, 512);
    gemm_k<4><<<dim3((BB + 127) / 128, 2), 256>>>(h1, nullptr, Wf2, bf2,
        outp, nullptr, nullptr, nullptr, nullptr, nullptr, nullptr, BB, 512, 256);

    if (out_size >= BB * EMBD + NN) {
        k_copy_batch<<<(NN + 255) / 256, 256>>>(outp + BB * EMBD);
    }
}